// round 3
// baseline (speedup 1.0000x reference)
#include <cuda_runtime.h>
#include <cuda_bf16.h>
#include <math.h>

#define Bx 8
#define Nx 4096
#define Ex 131072
#define Fx 64
#define CAP 128
#define CAPP (CAP + 2)
#define ALPHA 0.2f

// ---------------- scratch (device globals; zero-initialized at load) --------
__device__ __align__(16) float g_Wh[Bx * Nx * Fx];      // 8 MB, [b][n][f]
__device__ __align__(16) float g_ssrc[Bx * Nx];
__device__ __align__(16) float g_sdst[Bx * Nx];
__device__ __align__(16) int   g_cnt[Nx];               // reset by k_agg each run
__device__ __align__(16) int   g_bkt_dst[Nx * CAP];
__device__ __align__(16) float g_bkt_w[Nx * CAP];

// ---------------- K1: Wh = h@W (+ s_src/s_dst dots) + edge bucketing --------
__global__ __launch_bounds__(256) void k_gemm(const float* __restrict__ h,
                                              const float* __restrict__ W,
                                              const float* __restrict__ a,
                                              const int* __restrict__ ei,
                                              const float* __restrict__ ew) {
    __shared__ float sW[64 * 64];     // 16 KB
    __shared__ float sh[32][64];      // 8 KB
    const int tid = threadIdx.x;

    // edge bucketing: 128 edges per block (1024*128 = Ex)
    if (tid < 128) {
        int e = blockIdx.x * 128 + tid;
        int s = ei[e];
        int d = ei[Ex + e];
        float w = ew[e];
        int pos = atomicAdd(&g_cnt[s], 1);
        if (pos < CAP) {
            g_bkt_dst[s * CAP + pos] = d;
            g_bkt_w[s * CAP + pos]   = w;
        }
    }

    const int row0 = blockIdx.x * 32;
    #pragma unroll
    for (int i = 0; i < 16; i++) sW[tid + i * 256] = W[tid + i * 256];
    #pragma unroll
    for (int i = 0; i < 8; i++) {
        int idx = tid + i * 256;
        sh[idx >> 6][idx & 63] = h[row0 * 64 + idx];
    }
    __syncthreads();

    const int w  = tid >> 5;
    const int oo = tid & 31;
    const int r0 = w * 4;
    float2 acc0 = make_float2(0.f, 0.f), acc1 = acc0, acc2 = acc0, acc3 = acc0;

    #pragma unroll
    for (int k = 0; k < 64; k += 4) {
        float h0[4], h1[4], h2[4], h3[4];
        *(float4*)h0 = *(const float4*)&sh[r0 + 0][k];
        *(float4*)h1 = *(const float4*)&sh[r0 + 1][k];
        *(float4*)h2 = *(const float4*)&sh[r0 + 2][k];
        *(float4*)h3 = *(const float4*)&sh[r0 + 3][k];
        #pragma unroll
        for (int kk = 0; kk < 4; kk++) {
            float2 w2 = *(const float2*)&sW[(k + kk) * 64 + oo * 2];
            acc0.x = fmaf(h0[kk], w2.x, acc0.x); acc0.y = fmaf(h0[kk], w2.y, acc0.y);
            acc1.x = fmaf(h1[kk], w2.x, acc1.x); acc1.y = fmaf(h1[kk], w2.y, acc1.y);
            acc2.x = fmaf(h2[kk], w2.x, acc2.x); acc2.y = fmaf(h2[kk], w2.y, acc2.y);
            acc3.x = fmaf(h3[kk], w2.x, acc3.x); acc3.y = fmaf(h3[kk], w2.y, acc3.y);
        }
    }

    const float a1x = a[oo * 2],      a1y = a[oo * 2 + 1];
    const float a2x = a[64 + oo * 2], a2y = a[64 + oo * 2 + 1];
    float2 accs[4] = {acc0, acc1, acc2, acc3};
    #pragma unroll
    for (int i = 0; i < 4; i++) {
        const int row = row0 + r0 + i;
        *(float2*)&g_Wh[row * 64 + oo * 2] = accs[i];
        float p1 = accs[i].x * a1x + accs[i].y * a1y;
        float p2 = accs[i].x * a2x + accs[i].y * a2y;
        #pragma unroll
        for (int s = 16; s > 0; s >>= 1) {
            p1 += __shfl_xor_sync(0xffffffffu, p1, s);
            p2 += __shfl_xor_sync(0xffffffffu, p2, s);
        }
        if (oo == 0) { g_ssrc[row] = p1; g_sdst[row] = p2; }
    }
}

// ---------------- K2: softmax + aggregation, block per node ------------------
// 8 warps = 8 batches. Per-warp: compute ex, pack (byte_off, ex) into smem,
// then gather 2 edges/iteration with LDG.128 (half-warp per edge).
__global__ __launch_bounds__(256) void k_agg(float* __restrict__ out) {
    __shared__ int   sh_dst[CAPP];
    __shared__ float sh_w[CAPP];
    __shared__ uint2 sh_pk[8][CAPP];
    __shared__ int   sh_cnt;
    const int node = blockIdx.x;
    const int tid  = threadIdx.x;
    const int lane = tid & 31;
    const int b    = tid >> 5;

    if (tid == 0) {
        int c = g_cnt[node];
        sh_cnt = (c < CAP) ? c : CAP;
        g_cnt[node] = 0;                       // reset for next graph replay
    }
    __syncthreads();
    const int deg = sh_cnt;

    for (int j = tid; j < deg; j += 256) {
        sh_dst[j] = g_bkt_dst[node * CAP + j];
        sh_w[j]   = g_bkt_w[node * CAP + j];
    }
    __syncthreads();

    const float s1 = g_ssrc[b * Nx + node];
    const float* __restrict__ sdst_b = &g_sdst[b * Nx];
    const int nch = (deg + 31) >> 5;

    // e per lane, running max
    float ev[4];
    float m = -INFINITY;
    #pragma unroll
    for (int c = 0; c < 4; c++) {
        float e = -INFINITY;
        int j = c * 32 + lane;
        if (c < nch && j < deg) {
            float raw = s1 + __ldg(&sdst_b[sh_dst[j]]);
            e = raw > 0.f ? raw : ALPHA * raw;
            e *= sh_w[j];
        }
        ev[c] = e;
        m = fmaxf(m, e);
    }
    #pragma unroll
    for (int s = 16; s > 0; s >>= 1)
        m = fmaxf(m, __shfl_xor_sync(0xffffffffu, m, s));

    // exp + denom
    float dsum = 0.f;
    #pragma unroll
    for (int c = 0; c < 4; c++) {
        float e = (ev[c] != -INFINITY) ? __expf(ev[c] - m) : 0.f;
        ev[c] = e;
        dsum += e;
    }
    #pragma unroll
    for (int s = 16; s > 0; s >>= 1)
        dsum += __shfl_xor_sync(0xffffffffu, dsum, s);

    // pack (byte offset, ex) per warp
    #pragma unroll
    for (int c = 0; c < 4; c++) {
        int j = c * 32 + lane;
        if (c < nch && j < deg)
            sh_pk[b][j] = make_uint2((unsigned)(sh_dst[j] * 256), __float_as_uint(ev[c]));
    }
    if (lane == 0) {
        sh_pk[b][deg]     = make_uint2(0u, 0u);   // pad for odd deg
        sh_pk[b][deg + 1] = make_uint2(0u, 0u);
    }
    __syncwarp();

    // gather: half-warp per edge, 2 edges per iteration, float4 per lane
    const char* __restrict__ Whp = (const char*)g_Wh + (size_t)b * Nx * Fx * 4;
    const int half = lane >> 4;        // which of the 2 edges
    const int fl   = lane & 15;        // feature quad
    float4 acc = make_float4(0.f, 0.f, 0.f, 0.f);
    #pragma unroll 4
    for (int t = 0; t < deg; t += 2) {
        uint2 p = sh_pk[b][t + half];
        float4 v = *(const float4*)(Whp + p.x + fl * 16);
        float exv = __uint_as_float(p.y);
        acc.x = fmaf(exv, v.x, acc.x);
        acc.y = fmaf(exv, v.y, acc.y);
        acc.z = fmaf(exv, v.z, acc.z);
        acc.w = fmaf(exv, v.w, acc.w);
    }
    // combine the two half-warp partial sums
    acc.x += __shfl_xor_sync(0xffffffffu, acc.x, 16);
    acc.y += __shfl_xor_sync(0xffffffffu, acc.y, 16);
    acc.z += __shfl_xor_sync(0xffffffffu, acc.z, 16);
    acc.w += __shfl_xor_sync(0xffffffffu, acc.w, 16);

    if (lane < 16) {
        const float inv = (deg > 0) ? (1.0f / dsum) : 0.f;
        float h0 = acc.x * inv, h1 = acc.y * inv, h2 = acc.z * inv, h3 = acc.w * inv;
        float4 o;
        o.x = h0 > 0.f ? h0 : expm1f(h0);
        o.y = h1 > 0.f ? h1 : expm1f(h1);
        o.z = h2 > 0.f ? h2 : expm1f(h2);
        o.w = h3 > 0.f ? h3 : expm1f(h3);
        *(float4*)&out[(b * Nx + node) * 64 + fl * 4] = o;
    }
}

// ---------------- launch -----------------------------------------------------
extern "C" void kernel_launch(void* const* d_in, const int* in_sizes, int n_in,
                              void* d_out, int out_size) {
    const float* h  = (const float*)d_in[0];
    const int*   ei = (const int*)d_in[1];
    const float* ew = (const float*)d_in[2];
    const float* W  = (const float*)d_in[3];
    const float* a  = (const float*)d_in[4];
    float* out = (float*)d_out;

    k_gemm<<<(Bx * Nx) / 32, 256>>>(h, W, a, ei, ew);
    k_agg<<<Nx, 256>>>(out);
}

// round 4
// speedup vs baseline: 1.0190x; 1.0190x over previous
#include <cuda_runtime.h>
#include <cuda_bf16.h>
#include <math.h>

#define Bx 8
#define Nx 4096
#define Ex 131072
#define Fx 64
#define CAP 128
#define CAPP (CAP + 2)
#define ALPHA 0.2f

// ---------------- scratch (device globals; zero-initialized at load) --------
__device__ __align__(16) float g_Wh[Bx * Nx * Fx];      // 8 MB, [b][n][f]
__device__ __align__(16) float g_ssrc[Bx * Nx];
__device__ __align__(16) float g_sdst[Bx * Nx];
__device__ __align__(16) int   g_cnt[Nx];               // reset by k_agg each run
__device__ __align__(16) int   g_bkt_dst[Nx * CAP];
__device__ __align__(16) float g_bkt_w[Nx * CAP];

// ---------------- K1: Wh = h@W (+ s_src/s_dst dots) + edge bucketing --------
__global__ __launch_bounds__(256) void k_gemm(const float* __restrict__ h,
                                              const float* __restrict__ W,
                                              const float* __restrict__ a,
                                              const int* __restrict__ ei,
                                              const float* __restrict__ ew) {
    __shared__ float sW[64 * 64];     // 16 KB
    __shared__ float sh[32][64];      // 8 KB
    const int tid = threadIdx.x;

    // edge bucketing: 128 edges per block (1024*128 = Ex)
    if (tid < 128) {
        int e = blockIdx.x * 128 + tid;
        int s = ei[e];
        int d = ei[Ex + e];
        float w = ew[e];
        int pos = atomicAdd(&g_cnt[s], 1);
        if (pos < CAP) {
            g_bkt_dst[s * CAP + pos] = d;
            g_bkt_w[s * CAP + pos]   = w;
        }
    }

    const int row0 = blockIdx.x * 32;
    #pragma unroll
    for (int i = 0; i < 16; i++) sW[tid + i * 256] = W[tid + i * 256];
    #pragma unroll
    for (int i = 0; i < 8; i++) {
        int idx = tid + i * 256;
        sh[idx >> 6][idx & 63] = h[row0 * 64 + idx];
    }
    __syncthreads();

    const int w  = tid >> 5;
    const int oo = tid & 31;
    const int r0 = w * 4;
    float2 acc0 = make_float2(0.f, 0.f), acc1 = acc0, acc2 = acc0, acc3 = acc0;

    #pragma unroll
    for (int k = 0; k < 64; k += 4) {
        float h0[4], h1[4], h2[4], h3[4];
        *(float4*)h0 = *(const float4*)&sh[r0 + 0][k];
        *(float4*)h1 = *(const float4*)&sh[r0 + 1][k];
        *(float4*)h2 = *(const float4*)&sh[r0 + 2][k];
        *(float4*)h3 = *(const float4*)&sh[r0 + 3][k];
        #pragma unroll
        for (int kk = 0; kk < 4; kk++) {
            float2 w2 = *(const float2*)&sW[(k + kk) * 64 + oo * 2];
            acc0.x = fmaf(h0[kk], w2.x, acc0.x); acc0.y = fmaf(h0[kk], w2.y, acc0.y);
            acc1.x = fmaf(h1[kk], w2.x, acc1.x); acc1.y = fmaf(h1[kk], w2.y, acc1.y);
            acc2.x = fmaf(h2[kk], w2.x, acc2.x); acc2.y = fmaf(h2[kk], w2.y, acc2.y);
            acc3.x = fmaf(h3[kk], w2.x, acc3.x); acc3.y = fmaf(h3[kk], w2.y, acc3.y);
        }
    }

    const float a1x = a[oo * 2],      a1y = a[oo * 2 + 1];
    const float a2x = a[64 + oo * 2], a2y = a[64 + oo * 2 + 1];
    float2 accs[4] = {acc0, acc1, acc2, acc3};
    #pragma unroll
    for (int i = 0; i < 4; i++) {
        const int row = row0 + r0 + i;
        *(float2*)&g_Wh[row * 64 + oo * 2] = accs[i];
        float p1 = accs[i].x * a1x + accs[i].y * a1y;
        float p2 = accs[i].x * a2x + accs[i].y * a2y;
        #pragma unroll
        for (int s = 16; s > 0; s >>= 1) {
            p1 += __shfl_xor_sync(0xffffffffu, p1, s);
            p2 += __shfl_xor_sync(0xffffffffu, p2, s);
        }
        if (oo == 0) { g_ssrc[row] = p1; g_sdst[row] = p2; }
    }
}

// ---------------- K2: softmax + aggregation, block per node ------------------
// 8 warps = 8 batches. Per-warp: compute ex, pack (byte_off, ex) into smem,
// then gather 2 edges/iteration with LDG.128 (half-warp per edge).
__global__ __launch_bounds__(256) void k_agg(float* __restrict__ out) {
    __shared__ int   sh_dst[CAPP];
    __shared__ float sh_w[CAPP];
    __shared__ uint2 sh_pk[8][CAPP];
    __shared__ int   sh_cnt;
    const int node = blockIdx.x;
    const int tid  = threadIdx.x;
    const int lane = tid & 31;
    const int b    = tid >> 5;

    if (tid == 0) {
        int c = g_cnt[node];
        sh_cnt = (c < CAP) ? c : CAP;
        g_cnt[node] = 0;                       // reset for next graph replay
    }
    __syncthreads();
    const int deg = sh_cnt;

    for (int j = tid; j < deg; j += 256) {
        sh_dst[j] = g_bkt_dst[node * CAP + j];
        sh_w[j]   = g_bkt_w[node * CAP + j];
    }
    __syncthreads();

    const float s1 = g_ssrc[b * Nx + node];
    const float* __restrict__ sdst_b = &g_sdst[b * Nx];
    const int nch = (deg + 31) >> 5;

    // e per lane, running max
    float ev[4];
    float m = -INFINITY;
    #pragma unroll
    for (int c = 0; c < 4; c++) {
        float e = -INFINITY;
        int j = c * 32 + lane;
        if (c < nch && j < deg) {
            float raw = s1 + __ldg(&sdst_b[sh_dst[j]]);
            e = raw > 0.f ? raw : ALPHA * raw;
            e *= sh_w[j];
        }
        ev[c] = e;
        m = fmaxf(m, e);
    }
    #pragma unroll
    for (int s = 16; s > 0; s >>= 1)
        m = fmaxf(m, __shfl_xor_sync(0xffffffffu, m, s));

    // exp + denom
    float dsum = 0.f;
    #pragma unroll
    for (int c = 0; c < 4; c++) {
        float e = (ev[c] != -INFINITY) ? __expf(ev[c] - m) : 0.f;
        ev[c] = e;
        dsum += e;
    }
    #pragma unroll
    for (int s = 16; s > 0; s >>= 1)
        dsum += __shfl_xor_sync(0xffffffffu, dsum, s);

    // pack (byte offset, ex) per warp
    #pragma unroll
    for (int c = 0; c < 4; c++) {
        int j = c * 32 + lane;
        if (c < nch && j < deg)
            sh_pk[b][j] = make_uint2((unsigned)(sh_dst[j] * 256), __float_as_uint(ev[c]));
    }
    if (lane == 0) {
        sh_pk[b][deg]     = make_uint2(0u, 0u);   // pad for odd deg
        sh_pk[b][deg + 1] = make_uint2(0u, 0u);
    }
    __syncwarp();

    // gather: half-warp per edge, 2 edges per iteration, float4 per lane
    const char* __restrict__ Whp = (const char*)g_Wh + (size_t)b * Nx * Fx * 4;
    const int half = lane >> 4;        // which of the 2 edges
    const int fl   = lane & 15;        // feature quad
    float4 acc = make_float4(0.f, 0.f, 0.f, 0.f);
    #pragma unroll 4
    for (int t = 0; t < deg; t += 2) {
        uint2 p = sh_pk[b][t + half];
        float4 v = *(const float4*)(Whp + p.x + fl * 16);
        float exv = __uint_as_float(p.y);
        acc.x = fmaf(exv, v.x, acc.x);
        acc.y = fmaf(exv, v.y, acc.y);
        acc.z = fmaf(exv, v.z, acc.z);
        acc.w = fmaf(exv, v.w, acc.w);
    }
    // combine the two half-warp partial sums
    acc.x += __shfl_xor_sync(0xffffffffu, acc.x, 16);
    acc.y += __shfl_xor_sync(0xffffffffu, acc.y, 16);
    acc.z += __shfl_xor_sync(0xffffffffu, acc.z, 16);
    acc.w += __shfl_xor_sync(0xffffffffu, acc.w, 16);

    if (lane < 16) {
        const float inv = (deg > 0) ? (1.0f / dsum) : 0.f;
        float h0 = acc.x * inv, h1 = acc.y * inv, h2 = acc.z * inv, h3 = acc.w * inv;
        float4 o;
        o.x = h0 > 0.f ? h0 : expm1f(h0);
        o.y = h1 > 0.f ? h1 : expm1f(h1);
        o.z = h2 > 0.f ? h2 : expm1f(h2);
        o.w = h3 > 0.f ? h3 : expm1f(h3);
        *(float4*)&out[(b * Nx + node) * 64 + fl * 4] = o;
    }
}

// ---------------- launch -----------------------------------------------------
extern "C" void kernel_launch(void* const* d_in, const int* in_sizes, int n_in,
                              void* d_out, int out_size) {
    const float* h  = (const float*)d_in[0];
    const int*   ei = (const int*)d_in[1];
    const float* ew = (const float*)d_in[2];
    const float* W  = (const float*)d_in[3];
    const float* a  = (const float*)d_in[4];
    float* out = (float*)d_out;

    k_gemm<<<(Bx * Nx) / 32, 256>>>(h, W, a, ei, ew);
    k_agg<<<Nx, 256>>>(out);
}

// round 6
// speedup vs baseline: 1.1130x; 1.0922x over previous
#include <cuda_runtime.h>
#include <cuda_bf16.h>
#include <math.h>

#define Bx 8
#define Nx 4096
#define Ex 131072
#define Fx 64
#define CAP 128
#define CAPP (CAP + 2)
#define ALPHA 0.2f

// ---------------- scratch (device globals; zero-initialized at load) --------
__device__ __align__(16) float g_Wh[Bx * Nx * Fx];      // 8 MB, [b][n][f]
__device__ __align__(16) float g_ssrc[Bx * Nx];
__device__ __align__(16) float g_sdst[Bx * Nx];
__device__ __align__(16) int   g_cnt[Nx];               // reset by k_agg each run
__device__ __align__(16) int   g_bkt_dst[Nx * CAP];
__device__ __align__(16) float g_bkt_w[Nx * CAP];

// ---------------- K1: Wh = h@W (+ s_src/s_dst dots) + edge bucketing --------
// 512 blocks x 256 threads; 64 rows/block; warp handles 8 rows so each W
// LDS.64 feeds 16 FFMA. Each thread buckets exactly one edge (512*256 = Ex).
__global__ __launch_bounds__(256) void k_gemm(const float* __restrict__ h,
                                              const float* __restrict__ W,
                                              const float* __restrict__ a,
                                              const int* __restrict__ ei,
                                              const float* __restrict__ ew) {
    __shared__ float sW[64 * 64];     // 16 KB
    __shared__ float sh[64][64];      // 16 KB
    const int tid = threadIdx.x;

    // edge bucketing: 256 edges per block (512*256 = Ex)
    {
        int e = blockIdx.x * 256 + tid;
        int s = ei[e];
        int d = ei[Ex + e];
        float w = ew[e];
        int pos = atomicAdd(&g_cnt[s], 1);
        if (pos < CAP) {
            g_bkt_dst[s * CAP + pos] = d;
            g_bkt_w[s * CAP + pos]   = w;
        }
    }

    const int row0 = blockIdx.x * 64;
    #pragma unroll
    for (int i = 0; i < 16; i++) sW[tid + i * 256] = W[tid + i * 256];
    #pragma unroll
    for (int i = 0; i < 16; i++) {
        int idx = tid + i * 256;                 // 0..4095
        sh[idx >> 6][idx & 63] = h[row0 * 64 + idx];
    }
    __syncthreads();

    const int w  = tid >> 5;          // warp -> 8 rows
    const int oo = tid & 31;          // lane -> output pair
    const int r0 = w * 8;
    float2 acc[8];
    #pragma unroll
    for (int r = 0; r < 8; r++) acc[r] = make_float2(0.f, 0.f);

    #pragma unroll 2
    for (int k = 0; k < 64; k += 4) {
        float4 hr[8];
        #pragma unroll
        for (int r = 0; r < 8; r++) hr[r] = *(const float4*)&sh[r0 + r][k];
        #pragma unroll
        for (int kk = 0; kk < 4; kk++) {
            float2 w2 = *(const float2*)&sW[(k + kk) * 64 + oo * 2];
            const float* hp = (const float*)hr;
            #pragma unroll
            for (int r = 0; r < 8; r++) {
                float hv = hp[r * 4 + kk];
                acc[r].x = fmaf(hv, w2.x, acc[r].x);
                acc[r].y = fmaf(hv, w2.y, acc[r].y);
            }
        }
    }

    const float a1x = a[oo * 2],      a1y = a[oo * 2 + 1];
    const float a2x = a[64 + oo * 2], a2y = a[64 + oo * 2 + 1];
    #pragma unroll
    for (int r = 0; r < 8; r++) {
        const int row = row0 + r0 + r;
        *(float2*)&g_Wh[row * 64 + oo * 2] = acc[r];
        float p1 = acc[r].x * a1x + acc[r].y * a1y;
        float p2 = acc[r].x * a2x + acc[r].y * a2y;
        #pragma unroll
        for (int s = 16; s > 0; s >>= 1) {
            p1 += __shfl_xor_sync(0xffffffffu, p1, s);
            p2 += __shfl_xor_sync(0xffffffffu, p2, s);
        }
        if (oo == 0) { g_ssrc[row] = p1; g_sdst[row] = p2; }
    }
}

// ---------------- K2: softmax + aggregation, block per node ------------------
// 8 warps = 8 batches. Offsets shared block-wide (sh_off); ex per warp (sh_ex).
// Gather: half-warp per edge, 2 edges/iter, LDG.128 per lane.
__global__ __launch_bounds__(256) void k_agg(float* __restrict__ out) {
    __shared__ int   sh_dst[CAPP];
    __shared__ int   sh_off[CAPP];        // byte offsets, shared by all warps
    __shared__ float sh_w[CAPP];
    __shared__ float sh_ex[8][CAPP];      // per-warp ex
    __shared__ int   sh_cnt;
    const int node = blockIdx.x;
    const int tid  = threadIdx.x;
    const int lane = tid & 31;
    const int b    = tid >> 5;

    if (tid == 0) {
        int c = g_cnt[node];
        sh_cnt = (c < CAP) ? c : CAP;
        g_cnt[node] = 0;                  // reset for next graph replay
    }
    __syncthreads();
    const int deg = sh_cnt;

    for (int j = tid; j < deg; j += 256) {
        int d = g_bkt_dst[node * CAP + j];
        sh_dst[j] = d;
        sh_off[j] = d * 256;              // byte offset within a Wh plane
        sh_w[j]   = g_bkt_w[node * CAP + j];
    }
    if (tid == 0) { sh_off[deg] = 0; sh_off[deg + 1] = 0; }
    __syncthreads();

    const float s1 = g_ssrc[b * Nx + node];
    const float* __restrict__ sdst_b = &g_sdst[b * Nx];
    const int nch = (deg + 31) >> 5;

    // e per lane, running max
    float ev[4];
    float m = -INFINITY;
    #pragma unroll
    for (int c = 0; c < 4; c++) {
        float e = -INFINITY;
        int j = c * 32 + lane;
        if (c < nch && j < deg) {
            float raw = s1 + __ldg(&sdst_b[sh_dst[j]]);
            e = raw > 0.f ? raw : ALPHA * raw;
            e *= sh_w[j];
        }
        ev[c] = e;
        m = fmaxf(m, e);
    }
    #pragma unroll
    for (int s = 16; s > 0; s >>= 1)
        m = fmaxf(m, __shfl_xor_sync(0xffffffffu, m, s));

    // exp + denom, stage ex to smem
    float dsum = 0.f;
    #pragma unroll
    for (int c = 0; c < 4; c++) {
        float e = (ev[c] != -INFINITY) ? __expf(ev[c] - m) : 0.f;
        int j = c * 32 + lane;
        if (c < nch && j < deg) sh_ex[b][j] = e;
        dsum += e;
    }
    #pragma unroll
    for (int s = 16; s > 0; s >>= 1)
        dsum += __shfl_xor_sync(0xffffffffu, dsum, s);
    if (lane == 0) { sh_ex[b][deg] = 0.f; sh_ex[b][deg + 1] = 0.f; }
    __syncwarp();

    // gather: half-warp per edge, 2 edges per iteration, float4 per lane
    const char* __restrict__ Whp = (const char*)g_Wh + (size_t)b * Nx * Fx * 4;
    const int half = lane >> 4;
    const int fl   = lane & 15;
    float4 acc = make_float4(0.f, 0.f, 0.f, 0.f);
    #pragma unroll 4
    for (int t = 0; t < deg; t += 2) {
        float exv = sh_ex[b][t + half];
        int   off = sh_off[t + half];
        float4 v = *(const float4*)(Whp + off + fl * 16);
        acc.x = fmaf(exv, v.x, acc.x);
        acc.y = fmaf(exv, v.y, acc.y);
        acc.z = fmaf(exv, v.z, acc.z);
        acc.w = fmaf(exv, v.w, acc.w);
    }
    acc.x += __shfl_xor_sync(0xffffffffu, acc.x, 16);
    acc.y += __shfl_xor_sync(0xffffffffu, acc.y, 16);
    acc.z += __shfl_xor_sync(0xffffffffu, acc.z, 16);
    acc.w += __shfl_xor_sync(0xffffffffu, acc.w, 16);

    if (lane < 16) {
        const float inv = (deg > 0) ? (1.0f / dsum) : 0.f;
        float h0 = acc.x * inv, h1 = acc.y * inv, h2 = acc.z * inv, h3 = acc.w * inv;
        float4 o;
        o.x = h0 > 0.f ? h0 : expm1f(h0);
        o.y = h1 > 0.f ? h1 : expm1f(h1);
        o.z = h2 > 0.f ? h2 : expm1f(h2);
        o.w = h3 > 0.f ? h3 : expm1f(h3);
        *(float4*)&out[(b * Nx + node) * 64 + fl * 4] = o;
    }
}

// ---------------- launch -----------------------------------------------------
extern "C" void kernel_launch(void* const* d_in, const int* in_sizes, int n_in,
                              void* d_out, int out_size) {
    const float* h  = (const float*)d_in[0];
    const int*   ei = (const int*)d_in[1];
    const float* ew = (const float*)d_in[2];
    const float* W  = (const float*)d_in[3];
    const float* a  = (const float*)d_in[4];
    float* out = (float*)d_out;

    k_gemm<<<(Bx * Nx) / 64, 256>>>(h, W, a, ei, ew);
    k_agg<<<Nx, 256>>>(out);
}

// round 7
// speedup vs baseline: 1.3285x; 1.1937x over previous
#include <cuda_runtime.h>
#include <cuda_bf16.h>
#include <math.h>

#define Bx 8
#define Nx 4096
#define Ex 131072
#define Fx 64
#define CAP 128
#define CAPP (CAP + 2)
#define ALPHA 0.2f

// ---------------- scratch (device globals; zero-initialized at load) --------
__device__ __align__(16) float g_Wh[Bx * Nx * Fx];      // 8 MB, [b][n][f]
__device__ __align__(16) float g_ssrc[Bx * Nx];
__device__ __align__(16) float g_sdst[Bx * Nx];
__device__ __align__(16) int   g_cnt[Nx];               // reset by k_agg each run
__device__ __align__(16) int   g_bkt_dst[Nx * CAP];
__device__ __align__(16) float g_bkt_w[Nx * CAP];

// ---------------- K1: Wh = h@W (+ s_src/s_dst dots) + edge bucketing --------
// 512 blocks x 256 threads; 64 rows/block; warp handles 8 rows. float4
// prologue loads. Each thread buckets exactly one edge (512*256 = Ex).
__global__ __launch_bounds__(256) void k_gemm(const float* __restrict__ h,
                                              const float* __restrict__ W,
                                              const float* __restrict__ a,
                                              const int* __restrict__ ei,
                                              const float* __restrict__ ew) {
    __shared__ float sW[64 * 64];     // 16 KB
    __shared__ float sh[64][64];      // 16 KB
    const int tid = threadIdx.x;

    // edge bucketing: 256 edges per block (512*256 = Ex)
    {
        int e = blockIdx.x * 256 + tid;
        int s = ei[e];
        int d = ei[Ex + e];
        float w = ew[e];
        int pos = atomicAdd(&g_cnt[s], 1);
        if (pos < CAP) {
            g_bkt_dst[s * CAP + pos] = d;
            g_bkt_w[s * CAP + pos]   = w;
        }
    }

    const int row0 = blockIdx.x * 64;
    const float4* __restrict__ W4 = (const float4*)W;
    const float4* __restrict__ h4 = (const float4*)(h + row0 * 64);
    #pragma unroll
    for (int i = 0; i < 4; i++) ((float4*)sW)[tid + i * 256] = W4[tid + i * 256];
    #pragma unroll
    for (int i = 0; i < 4; i++) ((float4*)sh)[tid + i * 256] = h4[tid + i * 256];
    __syncthreads();

    const int w  = tid >> 5;          // warp -> 8 rows
    const int oo = tid & 31;          // lane -> output pair
    const int r0 = w * 8;
    float2 acc[8];
    #pragma unroll
    for (int r = 0; r < 8; r++) acc[r] = make_float2(0.f, 0.f);

    #pragma unroll 2
    for (int k = 0; k < 64; k += 4) {
        float4 hr[8];
        #pragma unroll
        for (int r = 0; r < 8; r++) hr[r] = *(const float4*)&sh[r0 + r][k];
        #pragma unroll
        for (int kk = 0; kk < 4; kk++) {
            float2 w2 = *(const float2*)&sW[(k + kk) * 64 + oo * 2];
            const float* hp = (const float*)hr;
            #pragma unroll
            for (int r = 0; r < 8; r++) {
                float hv = hp[r * 4 + kk];
                acc[r].x = fmaf(hv, w2.x, acc[r].x);
                acc[r].y = fmaf(hv, w2.y, acc[r].y);
            }
        }
    }

    const float a1x = a[oo * 2],      a1y = a[oo * 2 + 1];
    const float a2x = a[64 + oo * 2], a2y = a[64 + oo * 2 + 1];
    #pragma unroll
    for (int r = 0; r < 8; r++) {
        const int row = row0 + r0 + r;
        *(float2*)&g_Wh[row * 64 + oo * 2] = acc[r];
        float p1 = acc[r].x * a1x + acc[r].y * a1y;
        float p2 = acc[r].x * a2x + acc[r].y * a2y;
        #pragma unroll
        for (int s = 16; s > 0; s >>= 1) {
            p1 += __shfl_xor_sync(0xffffffffu, p1, s);
            p2 += __shfl_xor_sync(0xffffffffu, p2, s);
        }
        if (oo == 0) { g_ssrc[row] = p1; g_sdst[row] = p2; }
    }
}

// ---------------- K2: softmax + aggregation, 2 nodes per block ---------------
// 8 warps = 8 batches; each warp handles BOTH nodes interleaved for 2x MLP.
// Gather: half-warp per edge, 2 edges x 2 nodes per iteration (4 LDG.128).
// Epilogue: lanes 0-15 write node0, lanes 16-31 write node1 (no idle lanes).
__global__ __launch_bounds__(256) void k_agg(float* __restrict__ out) {
    __shared__ int   sh_dst[2][CAPP];
    __shared__ int   sh_off[2][CAPP];     // byte offsets, shared block-wide
    __shared__ float sh_w[2][CAPP];
    __shared__ float sh_ex[8][2][CAPP];   // per-warp, per-node ex
    __shared__ int   sh_cnt[2];
    const int node0 = blockIdx.x * 2;
    const int tid  = threadIdx.x;
    const int lane = tid & 31;
    const int b    = tid >> 5;

    if (tid < 2) {
        int c = g_cnt[node0 + tid];
        sh_cnt[tid] = (c < CAP) ? c : CAP;
        g_cnt[node0 + tid] = 0;           // reset for next graph replay
    }
    __syncthreads();
    const int deg0 = sh_cnt[0];
    const int deg1 = sh_cnt[1];
    const int dmax = deg0 > deg1 ? deg0 : deg1;

    #pragma unroll
    for (int u = 0; u < 2; u++) {
        const int dg = u == 0 ? deg0 : deg1;
        for (int j = tid; j < dg; j += 256) {
            int d = g_bkt_dst[(node0 + u) * CAP + j];
            sh_dst[u][j] = d;
            sh_off[u][j] = d * 256;
            sh_w[u][j]   = g_bkt_w[(node0 + u) * CAP + j];
        }
        for (int j = dg + tid; j < dmax + 2; j += 256) sh_off[u][j] = 0;
    }
    __syncthreads();

    const float s1_0 = g_ssrc[b * Nx + node0];
    const float s1_1 = g_ssrc[b * Nx + node0 + 1];
    const float* __restrict__ sdst_b = &g_sdst[b * Nx];

    // e per lane, both nodes interleaved, running max
    float ev0[4], ev1[4];
    float m0 = -INFINITY, m1 = -INFINITY;
    #pragma unroll
    for (int c = 0; c < 4; c++) {
        int j = c * 32 + lane;
        float e0 = -INFINITY, e1 = -INFINITY;
        if (j < deg0) {
            float raw = s1_0 + __ldg(&sdst_b[sh_dst[0][j]]);
            e0 = (raw > 0.f ? raw : ALPHA * raw) * sh_w[0][j];
        }
        if (j < deg1) {
            float raw = s1_1 + __ldg(&sdst_b[sh_dst[1][j]]);
            e1 = (raw > 0.f ? raw : ALPHA * raw) * sh_w[1][j];
        }
        ev0[c] = e0; ev1[c] = e1;
        m0 = fmaxf(m0, e0); m1 = fmaxf(m1, e1);
    }
    #pragma unroll
    for (int s = 16; s > 0; s >>= 1) {
        m0 = fmaxf(m0, __shfl_xor_sync(0xffffffffu, m0, s));
        m1 = fmaxf(m1, __shfl_xor_sync(0xffffffffu, m1, s));
    }

    // exp + denom, stage ex to smem (pad to dmax+2 with zeros)
    float ds0 = 0.f, ds1 = 0.f;
    #pragma unroll
    for (int c = 0; c < 4; c++) {
        int j = c * 32 + lane;
        float e0 = (ev0[c] != -INFINITY) ? __expf(ev0[c] - m0) : 0.f;
        float e1 = (ev1[c] != -INFINITY) ? __expf(ev1[c] - m1) : 0.f;
        if (j < deg0) sh_ex[b][0][j] = e0;
        if (j < deg1) sh_ex[b][1][j] = e1;
        ds0 += e0; ds1 += e1;
    }
    for (int j = deg0 + lane; j < dmax + 2; j += 32) sh_ex[b][0][j] = 0.f;
    for (int j = deg1 + lane; j < dmax + 2; j += 32) sh_ex[b][1][j] = 0.f;
    #pragma unroll
    for (int s = 16; s > 0; s >>= 1) {
        ds0 += __shfl_xor_sync(0xffffffffu, ds0, s);
        ds1 += __shfl_xor_sync(0xffffffffu, ds1, s);
    }
    __syncwarp();

    // gather: half-warp per edge, 2 edges x 2 nodes per iteration
    const char* __restrict__ Whp = (const char*)g_Wh + (size_t)b * Nx * Fx * 4;
    const int half = lane >> 4;
    const int fl   = lane & 15;
    float4 A0 = make_float4(0.f, 0.f, 0.f, 0.f);
    float4 A1 = make_float4(0.f, 0.f, 0.f, 0.f);
    #pragma unroll 4
    for (int t = 0; t < dmax; t += 2) {
        float ex0 = sh_ex[b][0][t + half];
        float ex1 = sh_ex[b][1][t + half];
        int   o0  = sh_off[0][t + half];
        int   o1  = sh_off[1][t + half];
        float4 v0 = *(const float4*)(Whp + o0 + fl * 16);
        float4 v1 = *(const float4*)(Whp + o1 + fl * 16);
        A0.x = fmaf(ex0, v0.x, A0.x); A0.y = fmaf(ex0, v0.y, A0.y);
        A0.z = fmaf(ex0, v0.z, A0.z); A0.w = fmaf(ex0, v0.w, A0.w);
        A1.x = fmaf(ex1, v1.x, A1.x); A1.y = fmaf(ex1, v1.y, A1.y);
        A1.z = fmaf(ex1, v1.z, A1.z); A1.w = fmaf(ex1, v1.w, A1.w);
    }
    A0.x += __shfl_xor_sync(0xffffffffu, A0.x, 16);
    A0.y += __shfl_xor_sync(0xffffffffu, A0.y, 16);
    A0.z += __shfl_xor_sync(0xffffffffu, A0.z, 16);
    A0.w += __shfl_xor_sync(0xffffffffu, A0.w, 16);
    A1.x += __shfl_xor_sync(0xffffffffu, A1.x, 16);
    A1.y += __shfl_xor_sync(0xffffffffu, A1.y, 16);
    A1.z += __shfl_xor_sync(0xffffffffu, A1.z, 16);
    A1.w += __shfl_xor_sync(0xffffffffu, A1.w, 16);

    // lanes 0-15 write node0; lanes 16-31 write node1
    const float4 accv = (half == 0) ? A0 : A1;
    const int   degh  = (half == 0) ? deg0 : deg1;
    const float dsh   = (half == 0) ? ds0 : ds1;
    const float inv = (degh > 0) ? (1.0f / dsh) : 0.f;
    float h0 = accv.x * inv, h1 = accv.y * inv, h2 = accv.z * inv, h3 = accv.w * inv;
    float4 o;
    o.x = h0 > 0.f ? h0 : expm1f(h0);
    o.y = h1 > 0.f ? h1 : expm1f(h1);
    o.z = h2 > 0.f ? h2 : expm1f(h2);
    o.w = h3 > 0.f ? h3 : expm1f(h3);
    *(float4*)&out[(b * Nx + node0 + half) * 64 + fl * 4] = o;
}

// ---------------- launch -----------------------------------------------------
extern "C" void kernel_launch(void* const* d_in, const int* in_sizes, int n_in,
                              void* d_out, int out_size) {
    const float* h  = (const float*)d_in[0];
    const int*   ei = (const int*)d_in[1];
    const float* ew = (const float*)d_in[2];
    const float* W  = (const float*)d_in[3];
    const float* a  = (const float*)d_in[4];
    float* out = (float*)d_out;

    k_gemm<<<(Bx * Nx) / 64, 256>>>(h, W, a, ei, ew);
    k_agg<<<Nx / 2, 256>>>(out);
}

// round 10
// speedup vs baseline: 1.4379x; 1.0823x over previous
#include <cuda_runtime.h>
#include <cuda_bf16.h>
#include <math.h>

#define Bx 8
#define Nx 4096
#define Ex 131072
#define Fx 64
#define CAP 128
#define CAPP (CAP + 2)
#define ALPHA 0.2f

// ---------------- scratch (device globals; zero-initialized at load) --------
__device__ __align__(16) float g_Wh[Bx * Nx * Fx];      // 8 MB, [b][n][f]
__device__ __align__(16) float g_ssrc[Bx * Nx];         // [b][n]
__device__ __align__(16) float g_sdstT[Nx * Bx];        // [n][b]  (32B per node)
__device__ __align__(16) int   g_cnt[Nx];               // reset by k_agg each run
__device__ __align__(16) int   g_bkt_dst[Nx * CAP];
__device__ __align__(16) float g_bkt_w[Nx * CAP];

// ---------------- K1: Wh = h@W (+ s_src/s_dstT dots) + edge bucketing -------
// 512 blocks x 256 threads; 64 rows/block; warp handles 8 rows. float4
// prologue loads. Each thread buckets exactly one edge (512*256 = Ex).
__global__ __launch_bounds__(256) void k_gemm(const float* __restrict__ h,
                                              const float* __restrict__ W,
                                              const float* __restrict__ a,
                                              const int* __restrict__ ei,
                                              const float* __restrict__ ew) {
    __shared__ float sW[64 * 64];     // 16 KB
    __shared__ float sh[64][64];      // 16 KB
    const int tid = threadIdx.x;

    // edge bucketing: 256 edges per block (512*256 = Ex)
    {
        int e = blockIdx.x * 256 + tid;
        int s = ei[e];
        int d = ei[Ex + e];
        float w = ew[e];
        int pos = atomicAdd(&g_cnt[s], 1);
        if (pos < CAP) {
            g_bkt_dst[s * CAP + pos] = d;
            g_bkt_w[s * CAP + pos]   = w;
        }
    }

    const int row0 = blockIdx.x * 64;
    const float4* __restrict__ W4 = (const float4*)W;
    const float4* __restrict__ h4 = (const float4*)(h + row0 * 64);
    #pragma unroll
    for (int i = 0; i < 4; i++) ((float4*)sW)[tid + i * 256] = W4[tid + i * 256];
    #pragma unroll
    for (int i = 0; i < 4; i++) ((float4*)sh)[tid + i * 256] = h4[tid + i * 256];
    __syncthreads();

    const int w  = tid >> 5;          // warp -> 8 rows
    const int oo = tid & 31;          // lane -> output pair
    const int r0 = w * 8;
    float2 acc[8];
    #pragma unroll
    for (int r = 0; r < 8; r++) acc[r] = make_float2(0.f, 0.f);

    #pragma unroll 2
    for (int k = 0; k < 64; k += 4) {
        float4 hr[8];
        #pragma unroll
        for (int r = 0; r < 8; r++) hr[r] = *(const float4*)&sh[r0 + r][k];
        #pragma unroll
        for (int kk = 0; kk < 4; kk++) {
            float2 w2 = *(const float2*)&sW[(k + kk) * 64 + oo * 2];
            const float* hp = (const float*)hr;
            #pragma unroll
            for (int r = 0; r < 8; r++) {
                float hv = hp[r * 4 + kk];
                acc[r].x = fmaf(hv, w2.x, acc[r].x);
                acc[r].y = fmaf(hv, w2.y, acc[r].y);
            }
        }
    }

    const float a1x = a[oo * 2],      a1y = a[oo * 2 + 1];
    const float a2x = a[64 + oo * 2], a2y = a[64 + oo * 2 + 1];
    #pragma unroll
    for (int r = 0; r < 8; r++) {
        const int row = row0 + r0 + r;      // = b*Nx + n
        *(float2*)&g_Wh[row * 64 + oo * 2] = acc[r];
        float p1 = acc[r].x * a1x + acc[r].y * a1y;
        float p2 = acc[r].x * a2x + acc[r].y * a2y;
        #pragma unroll
        for (int s = 16; s > 0; s >>= 1) {
            p1 += __shfl_xor_sync(0xffffffffu, p1, s);
            p2 += __shfl_xor_sync(0xffffffffu, p2, s);
        }
        if (oo == 0) {
            int n = row & (Nx - 1);
            int b = row >> 12;
            g_ssrc[row] = p1;
            g_sdstT[n * Bx + b] = p2;       // transposed: 8 batches contiguous
        }
    }
}

// ---------------- K2: softmax + aggregation, 4 nodes per block ---------------
// 512 threads = 16 warps. warp w: batch b = w&7, node group grp = w>>3 (2 nodes).
// Phase 0: 4 threads read+reset g_cnt into sh_cnt (sole readers -> no race).
// Phase 1 (block): one thread per (node u, slot j) stages dst-offset, weight,
//   and the full 8-batch s_dst row (32B) into padded smem (conflict-free).
// Phase 2 (warp): e -> max -> exp -> denom, stage ex to smem.
// Phase 3 (warp): half-warp per edge, 2 edges x 2 nodes per iter, LDG.128.
__global__ __launch_bounds__(512) void k_agg(float* __restrict__ out) {
    __shared__ int   sh_off[4][CAPP];        // Wh byte offsets (0-padded)
    __shared__ float sh_w[4][CAP];
    __shared__ float sh_sd[4][CAPP][9];      // staged sdstT rows, pad 9 = cf
    __shared__ float sh_ex[16][2][CAPP];     // per-warp per-node ex (0-padded)
    __shared__ int   sh_cnt[4];
    const int node0 = blockIdx.x * 4;
    const int tid  = threadIdx.x;
    const int lane = tid & 31;
    const int w    = tid >> 5;
    const int b    = w & 7;
    const int grp  = w >> 3;

    // Phase 0: counter read+reset by sole readers
    if (tid < 4) {
        int c = g_cnt[node0 + tid];
        sh_cnt[tid] = (c < CAP) ? c : CAP;
        g_cnt[node0 + tid] = 0;              // reset for next graph replay
    }
    __syncthreads();

    // Phase 1: stage buckets + sdstT. u = tid>>7 (0..3), j = tid&127.
    {
        const int u = tid >> 7;
        const int j = tid & 127;
        const int deg = sh_cnt[u];
        if (j < deg) {
            int d = g_bkt_dst[(node0 + u) * CAP + j];
            sh_off[u][j] = d * 256;
            sh_w[u][j]   = g_bkt_w[(node0 + u) * CAP + j];
            float4 lo = *(const float4*)&g_sdstT[d * 8];
            float4 hi = *(const float4*)&g_sdstT[d * 8 + 4];
            float* sd = sh_sd[u][j];
            sd[0] = lo.x; sd[1] = lo.y; sd[2] = lo.z; sd[3] = lo.w;
            sd[4] = hi.x; sd[5] = hi.y; sd[6] = hi.z; sd[7] = hi.w;
        } else {
            sh_off[u][j] = 0;
        }
        if (j < 2) sh_off[u][CAP + j] = 0;
    }
    __syncthreads();

    const int u0 = grp * 2, u1 = u0 + 1;
    const int deg0 = sh_cnt[u0];
    const int deg1 = sh_cnt[u1];
    const int dmax = deg0 > deg1 ? deg0 : deg1;

    const float s1_0 = g_ssrc[b * Nx + node0 + u0];
    const float s1_1 = g_ssrc[b * Nx + node0 + u1];

    // Phase 2: e per lane (LDS-fed), running max
    float ev0[4], ev1[4];
    float m0 = -INFINITY, m1 = -INFINITY;
    #pragma unroll
    for (int c = 0; c < 4; c++) {
        int j = c * 32 + lane;
        float e0 = -INFINITY, e1 = -INFINITY;
        if (j < deg0) {
            float raw = s1_0 + sh_sd[u0][j][b];
            e0 = (raw > 0.f ? raw : ALPHA * raw) * sh_w[u0][j];
        }
        if (j < deg1) {
            float raw = s1_1 + sh_sd[u1][j][b];
            e1 = (raw > 0.f ? raw : ALPHA * raw) * sh_w[u1][j];
        }
        ev0[c] = e0; ev1[c] = e1;
        m0 = fmaxf(m0, e0); m1 = fmaxf(m1, e1);
    }
    #pragma unroll
    for (int s = 16; s > 0; s >>= 1) {
        m0 = fmaxf(m0, __shfl_xor_sync(0xffffffffu, m0, s));
        m1 = fmaxf(m1, __shfl_xor_sync(0xffffffffu, m1, s));
    }

    float ds0 = 0.f, ds1 = 0.f;
    #pragma unroll
    for (int c = 0; c < 4; c++) {
        int j = c * 32 + lane;
        float e0 = (ev0[c] != -INFINITY) ? __expf(ev0[c] - m0) : 0.f;
        float e1 = (ev1[c] != -INFINITY) ? __expf(ev1[c] - m1) : 0.f;
        sh_ex[w][0][j] = e0;               // 0 beyond deg
        sh_ex[w][1][j] = e1;
        ds0 += e0; ds1 += e1;
    }
    if (lane < 2) { sh_ex[w][0][CAP + lane] = 0.f; sh_ex[w][1][CAP + lane] = 0.f; }
    #pragma unroll
    for (int s = 16; s > 0; s >>= 1) {
        ds0 += __shfl_xor_sync(0xffffffffu, ds0, s);
        ds1 += __shfl_xor_sync(0xffffffffu, ds1, s);
    }
    __syncwarp();

    // Phase 3: gather — half-warp per edge, 2 edges x 2 nodes per iteration
    const char* __restrict__ Whp = (const char*)g_Wh + (size_t)b * Nx * Fx * 4;
    const int half = lane >> 4;
    const int fl   = lane & 15;
    float4 A0 = make_float4(0.f, 0.f, 0.f, 0.f);
    float4 A1 = make_float4(0.f, 0.f, 0.f, 0.f);
    #pragma unroll 4
    for (int t = 0; t < dmax; t += 2) {
        float ex0 = sh_ex[w][0][t + half];
        float ex1 = sh_ex[w][1][t + half];
        int   o0  = sh_off[u0][t + half];
        int   o1  = sh_off[u1][t + half];
        float4 v0 = *(const float4*)(Whp + o0 + fl * 16);
        float4 v1 = *(const float4*)(Whp + o1 + fl * 16);
        A0.x = fmaf(ex0, v0.x, A0.x); A0.y = fmaf(ex0, v0.y, A0.y);
        A0.z = fmaf(ex0, v0.z, A0.z); A0.w = fmaf(ex0, v0.w, A0.w);
        A1.x = fmaf(ex1, v1.x, A1.x); A1.y = fmaf(ex1, v1.y, A1.y);
        A1.z = fmaf(ex1, v1.z, A1.z); A1.w = fmaf(ex1, v1.w, A1.w);
    }
    A0.x += __shfl_xor_sync(0xffffffffu, A0.x, 16);
    A0.y += __shfl_xor_sync(0xffffffffu, A0.y, 16);
    A0.z += __shfl_xor_sync(0xffffffffu, A0.z, 16);
    A0.w += __shfl_xor_sync(0xffffffffu, A0.w, 16);
    A1.x += __shfl_xor_sync(0xffffffffu, A1.x, 16);
    A1.y += __shfl_xor_sync(0xffffffffu, A1.y, 16);
    A1.z += __shfl_xor_sync(0xffffffffu, A1.z, 16);
    A1.w += __shfl_xor_sync(0xffffffffu, A1.w, 16);

    // lanes 0-15 write node u0; lanes 16-31 write node u1
    const float4 accv = (half == 0) ? A0 : A1;
    const int   degh  = (half == 0) ? deg0 : deg1;
    const float dsh   = (half == 0) ? ds0 : ds1;
    const float inv = (degh > 0) ? (1.0f / dsh) : 0.f;
    float h0 = accv.x * inv, h1 = accv.y * inv, h2 = accv.z * inv, h3 = accv.w * inv;
    float4 o;
    o.x = h0 > 0.f ? h0 : expm1f(h0);
    o.y = h1 > 0.f ? h1 : expm1f(h1);
    o.z = h2 > 0.f ? h2 : expm1f(h2);
    o.w = h3 > 0.f ? h3 : expm1f(h3);
    *(float4*)&out[(b * Nx + node0 + u0 + half) * 64 + fl * 4] = o;
}

// ---------------- launch -----------------------------------------------------
extern "C" void kernel_launch(void* const* d_in, const int* in_sizes, int n_in,
                              void* d_out, int out_size) {
    const float* h  = (const float*)d_in[0];
    const int*   ei = (const int*)d_in[1];
    const float* ew = (const float*)d_in[2];
    const float* W  = (const float*)d_in[3];
    const float* a  = (const float*)d_in[4];
    float* out = (float*)d_out;

    k_gemm<<<(Bx * Nx) / 64, 256>>>(h, W, a, ei, ew);
    k_agg<<<Nx / 4, 512>>>(out);
}